// round 16
// baseline (speedup 1.0000x reference)
#include <cuda_runtime.h>
#include <cuda_fp16.h>
#include <cstdint>

#define HW   16384
#define NB   4
#define WDIM 128
#define PITCHA 40      // elements; 80B rows (A, non-trans ldmatrix)
#define PITCHB 136     // elements; 272B rows (B fp16, trans ldmatrix)

// ---------------- scratch (__device__ globals) ------------------------------
__device__ __half g_Ahi[512 * 256];                 // rows 0-255 wv, 256-511 w1
__device__ __half g_Alo[512 * 256];
__device__ __half g_W2hi[128 * 256];                // w2 (64 rows used)
__device__ __half g_W2lo[128 * 256];
__device__ __half g_Uhi[(size_t)NB * 256 * HW];     // u hi [b][c][p] (written by gemm_h)
__device__ __half g_Hmhi[(size_t)NB * 256 * HW];    // h hi [b][c][p]
__device__ __half g_Hmlo[(size_t)NB * 256 * HW];
__device__ __align__(16) __half g_valh[(size_t)NB * 32 * HW * 8];  // value fp16 [b][head][p][ci]
__device__ float g_flow [(size_t)NB * 64 * HW];

// ---------------- helpers ---------------------------------------------------
__device__ __forceinline__ uint32_t smem_u32(const void* p) {
    uint32_t a;
    asm("{ .reg .u64 t; cvta.to.shared.u64 t, %1; cvt.u32.u64 %0, t; }" : "=r"(a) : "l"(p));
    return a;
}
__device__ __forceinline__ void ldsm_x4(uint32_t* r, uint32_t addr) {
    asm volatile("ldmatrix.sync.aligned.m8n8.x4.shared.b16 {%0,%1,%2,%3}, [%4];"
                 : "=r"(r[0]), "=r"(r[1]), "=r"(r[2]), "=r"(r[3]) : "r"(addr));
}
__device__ __forceinline__ void ldsm_x2t(uint32_t* r, uint32_t addr) {
    asm volatile("ldmatrix.sync.aligned.m8n8.x2.trans.shared.b16 {%0,%1}, [%2];"
                 : "=r"(r[0]), "=r"(r[1]) : "r"(addr));
}
__device__ __forceinline__ void mma16816(float* c, const uint32_t* a, const uint32_t* b) {
    asm volatile("mma.sync.aligned.m16n8k16.row.col.f32.f16.f16.f32 "
                 "{%0,%1,%2,%3}, {%4,%5,%6,%7}, {%8,%9}, {%0,%1,%2,%3};"
                 : "+f"(c[0]), "+f"(c[1]), "+f"(c[2]), "+f"(c[3])
                 : "r"(a[0]), "r"(a[1]), "r"(a[2]), "r"(a[3]), "r"(b[0]), "r"(b[1]));
}
__device__ __forceinline__ void cpa16(uint32_t dst, const void* src) {
    asm volatile("cp.async.cg.shared.global [%0], [%1], 16;" :: "r"(dst), "l"(src));
}
#define CP_COMMIT() asm volatile("cp.async.commit_group;" ::: "memory")
#define CP_WAIT0()  asm volatile("cp.async.wait_group 0;" ::: "memory")
#define CP_WAIT1()  asm volatile("cp.async.wait_group 1;" ::: "memory")

// ---------------------------------------------------------------------------
__global__ void prep_weights(const float* __restrict__ w1, const float* __restrict__ wv,
                             const float* __restrict__ w2)
{
    int idx = blockIdx.x * 256 + threadIdx.x;
    if (blockIdx.x < 512) {
        int r = idx >> 8, k = idx & 255;
        float x = (r < 256) ? wv[r * 256 + k] : w1[(r - 256) * 256 + k];
        __half h = __float2half_rn(x);
        g_Ahi[idx] = h;
        g_Alo[idx] = __float2half_rn(x - __half2float(h));
    } else {
        int i2 = idx - 512 * 256;
        int r = i2 >> 8, k = i2 & 255;
        float x = (r < 64) ? w2[r * 256 + k] : 0.f;
        __half h = __float2half_rn(x);
        g_W2hi[i2] = h;
        g_W2lo[i2] = __float2half_rn(x - __half2float(h));
    }
}

// ---------------------------------------------------------------------------
// gemm_h: h = relu(w1@u+b1) for ONE batch. Fused fp32->fp16 convert;
// mtile==0 exports uhi. 3-term, sequential MMA schedule. grid (2,128).
// ---------------------------------------------------------------------------
__global__ __launch_bounds__(256, 2) void gemm_h(const float* __restrict__ u,
                                                 const float* __restrict__ bias,
                                                 int b)
{
    constexpr int APL    = 128 * PITCHA * 2;
    constexpr int A_ST   = 2 * APL;
    constexpr int B32_ST = 32 * 528;
    constexpr int B16PL  = 32 * PITCHB * 2;
    constexpr int OFF_B32 = 2 * A_ST;
    constexpr int OFF_B16 = OFF_B32 + 2 * B32_ST;

    extern __shared__ __align__(16) char smem[];
    const uint32_t uS = smem_u32(smem);

    const int tid = threadIdx.x, lane = tid & 31, wid = tid >> 5;
    const int wm = wid >> 2, wn = wid & 3;
    const int mtile = blockIdx.x, ntile = blockIdx.y;
    const int n0 = ntile * 128;
    const int arow0 = 256 + mtile * 128;

    const __half* Agh = g_Ahi + (size_t)arow0 * 256;
    const __half* Agl = g_Alo + (size_t)arow0 * 256;
    const float*  Bg  = u + (size_t)b * 256 * HW + n0;
    __half* uhi_out = g_Uhi + (size_t)b * 256 * HW + n0;

    auto load_tiles = [&](int kt, int st) {
        const int k0 = kt * 32;
#pragma unroll
        for (int q = tid; q < 1024; q += 256) {
            const int pl = q >> 9, qq = q & 511;
            const int r = qq >> 2, c8 = (qq & 3) * 8;
            cpa16(uS + st * A_ST + pl * APL + (uint32_t)(r * PITCHA + c8) * 2,
                  (pl ? Agl : Agh) + (size_t)r * 256 + k0 + c8);
        }
#pragma unroll
        for (int q = tid; q < 1024; q += 256) {
            const int r = q >> 5, c = q & 31;
            cpa16(uS + OFF_B32 + st * B32_ST + (uint32_t)(r * 528 + c * 16),
                  Bg + (size_t)(k0 + r) * HW + c * 4);
        }
    };

    float acc[4][4][4];
#pragma unroll
    for (int mi = 0; mi < 4; mi++)
#pragma unroll
        for (int ni = 0; ni < 4; ni++)
#pragma unroll
            for (int e = 0; e < 4; e++) acc[mi][ni][e] = 0.f;

    load_tiles(0, 0); CP_COMMIT();

#pragma unroll 1
    for (int kt = 0; kt < 8; kt++) {
        const int st = kt & 1;
        const int k0 = kt * 32;
        CP_WAIT0();
        __syncthreads();

        {
            char* srcb = smem + OFF_B32 + st * B32_ST;
#pragma unroll
            for (int j = 0; j < 4; j++) {
                const int p = j * 256 + tid;
                const int r = p >> 5, c4 = p & 31;
                float4 v4 = *reinterpret_cast<const float4*>(srcb + r * 528 + c4 * 16);
                __half h0 = __float2half_rn(v4.x), h1 = __float2half_rn(v4.y);
                __half h2 = __float2half_rn(v4.z), h3 = __float2half_rn(v4.w);
                union { __half h[4]; uint2 q; } hh, ll;
                hh.h[0] = h0; hh.h[1] = h1; hh.h[2] = h2; hh.h[3] = h3;
                ll.h[0] = __float2half_rn(v4.x - __half2float(h0));
                ll.h[1] = __float2half_rn(v4.y - __half2float(h1));
                ll.h[2] = __float2half_rn(v4.z - __half2float(h2));
                ll.h[3] = __float2half_rn(v4.w - __half2float(h3));
                *reinterpret_cast<uint2*>(smem + OFF_B16 + r * 272 + c4 * 8) = hh.q;
                *reinterpret_cast<uint2*>(smem + OFF_B16 + B16PL + r * 272 + c4 * 8) = ll.q;
                if (mtile == 0)
                    *reinterpret_cast<uint2*>(uhi_out + (size_t)(k0 + r) * HW + c4 * 4) = hh.q;
            }
        }
        __syncthreads();

        if (kt < 7) { load_tiles(kt + 1, st ^ 1); CP_COMMIT(); }

        const uint32_t uAh = uS + st * A_ST, uAl = uAh + APL;
        const uint32_t uBh = uS + OFF_B16,   uBl = uBh + B16PL;
#pragma unroll
        for (int s = 0; s < 2; s++) {
            uint32_t ah[4][4], al[4][4];
            const uint32_t arow = (uint32_t)(wm * 64 + (lane & 15));
            const uint32_t aoff = 2u * (arow * PITCHA + s * 16 + (lane >> 4) * 8);
#pragma unroll
            for (int mi = 0; mi < 4; mi++) {
                const uint32_t o = aoff + 2u * (mi * 16 * PITCHA);
                ldsm_x4(ah[mi], uAh + o);
                ldsm_x4(al[mi], uAl + o);
            }
            const uint32_t bk = (uint32_t)(s * 16 + (lane & 15));
            const uint32_t brow = 2u * (bk * PITCHB);
#pragma unroll
            for (int ni = 0; ni < 4; ni++) {
                const uint32_t o = brow + 2u * (wn * 32 + ni * 8);
                uint32_t bh[2], bl[2];
                ldsm_x2t(bh, uBh + o);
                ldsm_x2t(bl, uBl + o);
#pragma unroll
                for (int mi = 0; mi < 4; mi++) {
                    mma16816(acc[mi][ni], ah[mi], bh);
                    mma16816(acc[mi][ni], ah[mi], bl);
                    mma16816(acc[mi][ni], al[mi], bh);
                }
            }
        }
    }

    const int qr = lane >> 2, qc = (lane & 3) * 2;
#pragma unroll
    for (int mi = 0; mi < 4; mi++) {
        const int c = mtile * 128 + wm * 64 + mi * 16 + qr;
        const float b0f = bias[c], b1f = bias[c + 8];
        __half* oh0 = g_Hmhi + ((size_t)b * 256 + c) * HW + n0;
        __half* ol0 = g_Hmlo + ((size_t)b * 256 + c) * HW + n0;
#pragma unroll
        for (int ni = 0; ni < 4; ni++) {
            const int n = wn * 32 + ni * 8 + qc;
#pragma unroll
            for (int hf = 0; hf < 2; hf++) {
                const float bb = hf ? b1f : b0f;
                float x0 = fmaxf(acc[mi][ni][hf * 2 + 0] + bb, 0.f);
                float x1 = fmaxf(acc[mi][ni][hf * 2 + 1] + bb, 0.f);
                __half h0 = __float2half_rn(x0);
                __half h1 = __float2half_rn(x1);
                union { __half v[2]; uint32_t q; } hh, ll;
                hh.v[0] = h0; hh.v[1] = h1;
                ll.v[0] = __float2half_rn(x0 - __half2float(h0));
                ll.v[1] = __float2half_rn(x1 - __half2float(h1));
                const size_t off = (size_t)(hf * 8) * HW + n;
                *reinterpret_cast<uint32_t*>(oh0 + off) = hh.q;
                *reinterpret_cast<uint32_t*>(ol0 + off) = ll.q;
            }
        }
    }
}

// ---------------------------------------------------------------------------
// gemm_vf: ONE batch. mtile 0,1 = value (1-term, fp16 head-major out).
//          mtile 2   = flow  (3-term, BM=64). grid (3,128).
// Single kernel so the CTA scheduler packs both workloads in one wave set.
// ---------------------------------------------------------------------------
__global__ __launch_bounds__(256, 2) void gemm_vf(const float* __restrict__ biasV,
                                                  const float* __restrict__ biasF,
                                                  int b)
{
    extern __shared__ __align__(16) char smem[];
    const uint32_t uS = smem_u32(smem);

    const int tid = threadIdx.x, lane = tid & 31, wid = tid >> 5;
    const int wm = wid >> 2, wn = wid & 3;
    const int mtile = blockIdx.x, ntile = blockIdx.y;
    const int n0 = ntile * 128;
    const int qr = lane >> 2, qc = (lane & 3) * 2;

    if (mtile < 2) {
        // ================= value path =================
        constexpr int APL   = 128 * PITCHA * 2;
        constexpr int BPL   = 32 * PITCHB * 2;
        constexpr int STAGE = APL + BPL;

        const __half* Ag = g_Ahi + (size_t)(mtile * 128) * 256;
        const __half* Bg = g_Uhi + (size_t)b * 256 * HW + n0;

        auto load_tiles = [&](int kt, int st) {
            const int k0 = kt * 32;
#pragma unroll
            for (int q = tid; q < 512; q += 256) {
                const int r = q >> 2, c8 = (q & 3) * 8;
                cpa16(uS + st * STAGE + (uint32_t)(r * PITCHA + c8) * 2,
                      Ag + (size_t)r * 256 + k0 + c8);
            }
#pragma unroll
            for (int q = tid; q < 512; q += 256) {
                const int r = q >> 4, c8 = (q & 15) * 8;
                cpa16(uS + st * STAGE + APL + (uint32_t)(r * PITCHB + c8) * 2,
                      Bg + (size_t)(k0 + r) * HW + c8);
            }
        };

        float acc[4][4][4];
#pragma unroll
        for (int mi = 0; mi < 4; mi++)
#pragma unroll
            for (int ni = 0; ni < 4; ni++)
#pragma unroll
                for (int e = 0; e < 4; e++) acc[mi][ni][e] = 0.f;

        load_tiles(0, 0); CP_COMMIT();
        load_tiles(1, 1); CP_COMMIT();

#pragma unroll 1
        for (int kt = 0; kt < 8; kt++) {
            const int st = kt % 3;
            if (kt < 7) { CP_WAIT1(); } else { CP_WAIT0(); }
            __syncthreads();

            const uint32_t uAh = uS + (uint32_t)st * STAGE;
            const uint32_t uBh = uAh + APL;
#pragma unroll
            for (int s = 0; s < 2; s++) {
                uint32_t ah[4][4];
                const uint32_t arow = (uint32_t)(wm * 64 + (lane & 15));
                const uint32_t aoff = 2u * (arow * PITCHA + s * 16 + (lane >> 4) * 8);
#pragma unroll
                for (int mi = 0; mi < 4; mi++)
                    ldsm_x4(ah[mi], uAh + aoff + 2u * (mi * 16 * PITCHA));
                const uint32_t bk = (uint32_t)(s * 16 + (lane & 15));
                const uint32_t brow = 2u * (bk * PITCHB);
#pragma unroll
                for (int ni = 0; ni < 4; ni++) {
                    uint32_t bh[2];
                    ldsm_x2t(bh, uBh + brow + 2u * (wn * 32 + ni * 8));
#pragma unroll
                    for (int mi = 0; mi < 4; mi++)
                        mma16816(acc[mi][ni], ah[mi], bh);
                }
            }
            if (kt + 2 < 8) { load_tiles(kt + 2, (kt + 2) % 3); CP_COMMIT(); }
        }

        // epilogue: smem reshuffle -> fp16 head-major
        __syncthreads();
        __half* sv = reinterpret_cast<__half*>(smem);
#pragma unroll
        for (int mi = 0; mi < 4; mi++) {
#pragma unroll
            for (int hf = 0; hf < 2; hf++) {
                const int cl = wm * 64 + mi * 16 + qr + hf * 8;
                const float bb = biasV[mtile * 128 + cl];
                const int hd = cl >> 3, ci = cl & 7;
#pragma unroll
                for (int ni = 0; ni < 4; ni++) {
                    const int n = wn * 32 + ni * 8 + qc;
                    sv[(hd * 128 + n)     * 8 + ci] = __float2half_rn(acc[mi][ni][hf * 2 + 0] + bb);
                    sv[(hd * 128 + n + 1) * 8 + ci] = __float2half_rn(acc[mi][ni][hf * 2 + 1] + bb);
                }
            }
        }
        __syncthreads();
#pragma unroll
        for (int q = tid; q < 2048; q += 256) {
            const int hd = q >> 7, p = q & 127;
            uint4 v = *reinterpret_cast<const uint4*>(sv + (hd * 128 + p) * 8);
            *reinterpret_cast<uint4*>(g_valh +
                (((size_t)b * 32 + mtile * 16 + hd) * HW + n0 + p) * 8) = v;
        }
    } else {
        // ================= flow path =================
        constexpr int ROWS = 64, MI = 2;
        constexpr int APLANE = ROWS * PITCHA * 2;
        constexpr int A_BUF  = 2 * APLANE;
        constexpr int BPLANE = 32 * PITCHB * 2;
        constexpr int STAGE  = A_BUF + 2 * BPLANE;
        constexpr int ACH    = ROWS * 4;

        const __half* Ag[2] = { g_W2hi, g_W2lo };
        const __half* Bg[2] = { g_Hmhi + (size_t)b * 256 * HW + n0,
                                g_Hmlo + (size_t)b * 256 * HW + n0 };

        auto load_tiles = [&](int kt, int st) {
            const int k0 = kt * 32;
#pragma unroll
            for (int q = tid; q < 2 * ACH; q += 256) {
                const int pl = q / ACH, qq = q % ACH;
                const int r = qq >> 2, c8 = (qq & 3) * 8;
                cpa16(uS + st * STAGE + pl * APLANE + (uint32_t)(r * PITCHA + c8) * 2,
                      Ag[pl] + (size_t)r * 256 + k0 + c8);
            }
#pragma unroll
            for (int q = tid; q < 1024; q += 256) {
                const int pl = q >> 9, qq = q & 511;
                const int r = qq >> 4, c8 = (qq & 15) * 8;
                cpa16(uS + st * STAGE + A_BUF + pl * BPLANE + (uint32_t)(r * PITCHB + c8) * 2,
                      Bg[pl] + (size_t)(k0 + r) * HW + c8);
            }
        };

        float acc[MI][4][4];
#pragma unroll
        for (int mi = 0; mi < MI; mi++)
#pragma unroll
            for (int ni = 0; ni < 4; ni++)
#pragma unroll
                for (int e = 0; e < 4; e++) acc[mi][ni][e] = 0.f;

        load_tiles(0, 0); CP_COMMIT();
        load_tiles(1, 1); CP_COMMIT();

#pragma unroll 1
        for (int kt = 0; kt < 8; kt++) {
            const int st = kt % 3;
            if (kt < 7) { CP_WAIT1(); } else { CP_WAIT0(); }
            __syncthreads();

            const uint32_t uAh = uS + (uint32_t)st * STAGE, uAl = uAh + APLANE;
            const uint32_t uBh = uAh + A_BUF,               uBl = uBh + BPLANE;
#pragma unroll
            for (int s = 0; s < 2; s++) {
                uint32_t ah[MI][4], al[MI][4];
                const uint32_t arow = (uint32_t)(wm * 32 + (lane & 15));
                const uint32_t aoff = 2u * (arow * PITCHA + s * 16 + (lane >> 4) * 8);
#pragma unroll
                for (int mi = 0; mi < MI; mi++) {
                    const uint32_t o = aoff + 2u * (mi * 16 * PITCHA);
                    ldsm_x4(ah[mi], uAh + o);
                    ldsm_x4(al[mi], uAl + o);
                }
                const uint32_t bk = (uint32_t)(s * 16 + (lane & 15));
                const uint32_t brow = 2u * (bk * PITCHB);
#pragma unroll
                for (int ni = 0; ni < 4; ni++) {
                    const uint32_t o = brow + 2u * (wn * 32 + ni * 8);
                    uint32_t bh[2], bl[2];
                    ldsm_x2t(bh, uBh + o);
                    ldsm_x2t(bl, uBl + o);
#pragma unroll
                    for (int mi = 0; mi < MI; mi++) {
                        mma16816(acc[mi][ni], ah[mi], bh);
                        mma16816(acc[mi][ni], ah[mi], bl);
                        mma16816(acc[mi][ni], al[mi], bh);
                    }
                }
            }
            if (kt + 2 < 8) { load_tiles(kt + 2, (kt + 2) % 3); CP_COMMIT(); }
        }

#pragma unroll
        for (int mi = 0; mi < MI; mi++) {
            const int m0 = wm * 32 + mi * 16 + qr;
            const float b0f = biasF[m0], b1f = biasF[m0 + 8];
            float* o0 = g_flow + ((size_t)b * 64 + m0) * HW + n0;
            float* o1 = o0 + (size_t)8 * HW;
#pragma unroll
            for (int ni = 0; ni < 4; ni++) {
                const int n = wn * 32 + ni * 8 + qc;
                float2 v0 = {acc[mi][ni][0] + b0f, acc[mi][ni][1] + b0f};
                float2 v1 = {acc[mi][ni][2] + b1f, acc[mi][ni][3] + b1f};
                *(float2*)&o0[n] = v0;
                *(float2*)&o1[n] = v1;
            }
        }
    }
}

// ---------------------------------------------------------------------------
__global__ __launch_bounds__(256)
void warp_gather_kernel(float* __restrict__ out)
{
    const int x = threadIdx.x;
    const int y = blockIdx.x * 2 + threadIdx.y;
    const int bh = blockIdx.y;
    const int b = bh >> 5, head = bh & 31;

    const float* fb = g_flow + ((size_t)b * 64 + head * 2) * HW + y * WDIM + x;
    const float fx = fb[0];
    const float fy = fb[HW];

    const float gx = fmaf((float)x, 2.f / 127.f, -1.f) + fx;
    const float gy = fmaf((float)y, 2.f / 127.f, -1.f) + fy;
    const float ix = (gx + 1.f) * 63.5f;
    const float iy = (gy + 1.f) * 63.5f;

    const float x0f = floorf(ix), y0f = floorf(iy);
    const float dx = ix - x0f, dy = iy - y0f;
    const int x0 = (int)x0f, y0 = (int)y0f;
    const int x1 = x0 + 1,   y1 = y0 + 1;

    const bool vx0 = (x0 >= 0) & (x0 < WDIM);
    const bool vx1 = (x1 >= 0) & (x1 < WDIM);
    const bool vy0 = (y0 >= 0) & (y0 < WDIM);
    const bool vy1 = (y1 >= 0) & (y1 < WDIM);

    const int x0c = min(max(x0, 0), WDIM - 1);
    const int x1c = min(max(x1, 0), WDIM - 1);
    const int y0c = min(max(y0, 0), WDIM - 1);
    const int y1c = min(max(y1, 0), WDIM - 1);

    const float w00 = (1.f - dx) * (1.f - dy) * (float)(vx0 & vy0);
    const float w01 = dx * (1.f - dy)         * (float)(vx1 & vy0);
    const float w10 = (1.f - dx) * dy         * (float)(vx0 & vy1);
    const float w11 = dx * dy                 * (float)(vx1 & vy1);

    const __half* vb = g_valh + ((size_t)b * 32 + head) * HW * 8;
    const uint4 q00 = *reinterpret_cast<const uint4*>(vb + (size_t)(y0c * WDIM + x0c) * 8);
    const uint4 q01 = *reinterpret_cast<const uint4*>(vb + (size_t)(y0c * WDIM + x1c) * 8);
    const uint4 q10 = *reinterpret_cast<const uint4*>(vb + (size_t)(y1c * WDIM + x0c) * 8);
    const uint4 q11 = *reinterpret_cast<const uint4*>(vb + (size_t)(y1c * WDIM + x1c) * 8);

    float r[8];
    {
        const __half2* h00 = reinterpret_cast<const __half2*>(&q00);
        const __half2* h01 = reinterpret_cast<const __half2*>(&q01);
        const __half2* h10 = reinterpret_cast<const __half2*>(&q10);
        const __half2* h11 = reinterpret_cast<const __half2*>(&q11);
#pragma unroll
        for (int j = 0; j < 4; j++) {
            float2 a = __half22float2(h00[j]);
            float2 c = __half22float2(h01[j]);
            float2 d = __half22float2(h10[j]);
            float2 e = __half22float2(h11[j]);
            r[j * 2 + 0] = w00 * a.x + w01 * c.x + w10 * d.x + w11 * e.x;
            r[j * 2 + 1] = w00 * a.y + w01 * c.y + w10 * d.y + w11 * e.y;
        }
    }

    float* ob = out + ((size_t)b * 256 + head * 8) * HW + y * WDIM + x;
#pragma unroll
    for (int ci = 0; ci < 8; ci++)
        ob[(size_t)ci * HW] = r[ci];
}

// ---------------------------------------------------------------------------
extern "C" void kernel_launch(void* const* d_in, const int* in_sizes, int n_in,
                              void* d_out, int out_size)
{
    const float* u  = (const float*)d_in[0];
    const float* w1 = (const float*)d_in[1];
    const float* b1 = (const float*)d_in[2];
    const float* w2 = (const float*)d_in[3];
    const float* b2 = (const float*)d_in[4];
    const float* wv = (const float*)d_in[5];
    const float* bv = (const float*)d_in[6];
    float* out = (float*)d_out;

    constexpr int SM_H  = 2 * (2 * 128 * PITCHA * 2) + 2 * (32 * 528) + 2 * (32 * PITCHB * 2); // 92160
    constexpr int SM_VF = 3 * (2 * 2 * 64 * PITCHA + 2 * 2 * 32 * PITCHB);                     // 82944 (max of paths)

    static cudaStream_t s2;
    static cudaEvent_t evH[NB], evVF[NB];
    static bool init = false;
    if (!init) {
        cudaFuncSetAttribute(gemm_h,  cudaFuncAttributeMaxDynamicSharedMemorySize, SM_H);
        cudaFuncSetAttribute(gemm_vf, cudaFuncAttributeMaxDynamicSharedMemorySize, SM_VF);
        cudaStreamCreateWithFlags(&s2, cudaStreamNonBlocking);
        for (int b = 0; b < NB; b++) {
            cudaEventCreateWithFlags(&evH[b], cudaEventDisableTiming);
            cudaEventCreateWithFlags(&evVF[b], cudaEventDisableTiming);
        }
        init = true;
    }

    prep_weights<<<640, 256>>>(w1, wv, w2);

    for (int b = 0; b < NB; b++) {
        gemm_h<<<dim3(2, 128), 256, SM_H>>>(u, b1, b);
        cudaEventRecord(evH[b], 0);
        cudaStreamWaitEvent(s2, evH[b], 0);
        gemm_vf<<<dim3(3, 128), 256, SM_VF, s2>>>(bv, b2, b);
        cudaEventRecord(evVF[b], s2);
    }
    for (int b = 0; b < NB; b++)
        cudaStreamWaitEvent(0, evVF[b], 0);
    warp_gather_kernel<<<dim3(64, 128), dim3(128, 2)>>>(out);
}

// round 17
// speedup vs baseline: 1.1511x; 1.1511x over previous
#include <cuda_runtime.h>
#include <cuda_fp16.h>
#include <cstdint>

#define HW   16384
#define NB   4
#define WDIM 128
#define PITCHA 40      // elements; 80B rows (A, non-trans ldmatrix)
#define PITCHB 136     // elements; 272B rows (B fp16, trans ldmatrix)

// ---------------- scratch (__device__ globals) ------------------------------
__device__ __half g_Ahi[512 * 256];                 // rows 0-255 wv, 256-511 w1
__device__ __half g_Alo[512 * 256];
__device__ __half g_W2hi[128 * 256];                // w2 (64 rows used)
__device__ __half g_W2lo[128 * 256];
__device__ __half g_Uhi[(size_t)NB * 256 * HW];     // u hi [b][c][p] (written by gemm_h)
__device__ __half g_Hmhi[(size_t)NB * 256 * HW];    // h hi [b][c][p]
__device__ __half g_Hmlo[(size_t)NB * 256 * HW];
__device__ __align__(16) __half g_valh[(size_t)NB * 32 * HW * 8];  // value fp16 [b][head][p][ci]
__device__ float g_flow [(size_t)NB * 64 * HW];

// ---------------- helpers ---------------------------------------------------
__device__ __forceinline__ uint32_t smem_u32(const void* p) {
    uint32_t a;
    asm("{ .reg .u64 t; cvta.to.shared.u64 t, %1; cvt.u32.u64 %0, t; }" : "=r"(a) : "l"(p));
    return a;
}
__device__ __forceinline__ void ldsm_x4(uint32_t* r, uint32_t addr) {
    asm volatile("ldmatrix.sync.aligned.m8n8.x4.shared.b16 {%0,%1,%2,%3}, [%4];"
                 : "=r"(r[0]), "=r"(r[1]), "=r"(r[2]), "=r"(r[3]) : "r"(addr));
}
__device__ __forceinline__ void ldsm_x2t(uint32_t* r, uint32_t addr) {
    asm volatile("ldmatrix.sync.aligned.m8n8.x2.trans.shared.b16 {%0,%1}, [%2];"
                 : "=r"(r[0]), "=r"(r[1]) : "r"(addr));
}
__device__ __forceinline__ void mma16816(float* c, const uint32_t* a, const uint32_t* b) {
    asm volatile("mma.sync.aligned.m16n8k16.row.col.f32.f16.f16.f32 "
                 "{%0,%1,%2,%3}, {%4,%5,%6,%7}, {%8,%9}, {%0,%1,%2,%3};"
                 : "+f"(c[0]), "+f"(c[1]), "+f"(c[2]), "+f"(c[3])
                 : "r"(a[0]), "r"(a[1]), "r"(a[2]), "r"(a[3]), "r"(b[0]), "r"(b[1]));
}
__device__ __forceinline__ void cpa16(uint32_t dst, const void* src) {
    asm volatile("cp.async.cg.shared.global [%0], [%1], 16;" :: "r"(dst), "l"(src));
}
#define CP_COMMIT() asm volatile("cp.async.commit_group;" ::: "memory")
#define CP_WAIT0()  asm volatile("cp.async.wait_group 0;" ::: "memory")
#define CP_WAIT1()  asm volatile("cp.async.wait_group 1;" ::: "memory")

// ---------------------------------------------------------------------------
__global__ void prep_weights(const float* __restrict__ w1, const float* __restrict__ wv,
                             const float* __restrict__ w2)
{
    int idx = blockIdx.x * 256 + threadIdx.x;
    if (blockIdx.x < 512) {
        int r = idx >> 8, k = idx & 255;
        float x = (r < 256) ? wv[r * 256 + k] : w1[(r - 256) * 256 + k];
        __half h = __float2half_rn(x);
        g_Ahi[idx] = h;
        g_Alo[idx] = __float2half_rn(x - __half2float(h));
    } else {
        int i2 = idx - 512 * 256;
        int r = i2 >> 8, k = i2 & 255;
        float x = (r < 64) ? w2[r * 256 + k] : 0.f;
        __half h = __float2half_rn(x);
        g_W2hi[i2] = h;
        g_W2lo[i2] = __float2half_rn(x - __half2float(h));
    }
}

// ---------------------------------------------------------------------------
// gemm_h: h = relu(w1@u+b1), full batch. Fused fp32->fp16 convert;
// mtile==0 exports uhi. 3-term, sequential MMA schedule. grid (2,128,NB).
// ---------------------------------------------------------------------------
__global__ __launch_bounds__(256, 2) void gemm_h(const float* __restrict__ u,
                                                 const float* __restrict__ bias)
{
    constexpr int APL    = 128 * PITCHA * 2;
    constexpr int A_ST   = 2 * APL;
    constexpr int B32_ST = 32 * 528;
    constexpr int B16PL  = 32 * PITCHB * 2;
    constexpr int OFF_B32 = 2 * A_ST;
    constexpr int OFF_B16 = OFF_B32 + 2 * B32_ST;

    extern __shared__ __align__(16) char smem[];
    const uint32_t uS = smem_u32(smem);

    const int tid = threadIdx.x, lane = tid & 31, wid = tid >> 5;
    const int wm = wid >> 2, wn = wid & 3;
    const int mtile = blockIdx.x, ntile = blockIdx.y, b = blockIdx.z;
    const int n0 = ntile * 128;
    const int arow0 = 256 + mtile * 128;

    const __half* Agh = g_Ahi + (size_t)arow0 * 256;
    const __half* Agl = g_Alo + (size_t)arow0 * 256;
    const float*  Bg  = u + (size_t)b * 256 * HW + n0;
    __half* uhi_out = g_Uhi + (size_t)b * 256 * HW + n0;

    auto load_tiles = [&](int kt, int st) {
        const int k0 = kt * 32;
#pragma unroll
        for (int q = tid; q < 1024; q += 256) {
            const int pl = q >> 9, qq = q & 511;
            const int r = qq >> 2, c8 = (qq & 3) * 8;
            cpa16(uS + st * A_ST + pl * APL + (uint32_t)(r * PITCHA + c8) * 2,
                  (pl ? Agl : Agh) + (size_t)r * 256 + k0 + c8);
        }
#pragma unroll
        for (int q = tid; q < 1024; q += 256) {
            const int r = q >> 5, c = q & 31;
            cpa16(uS + OFF_B32 + st * B32_ST + (uint32_t)(r * 528 + c * 16),
                  Bg + (size_t)(k0 + r) * HW + c * 4);
        }
    };

    float acc[4][4][4];
#pragma unroll
    for (int mi = 0; mi < 4; mi++)
#pragma unroll
        for (int ni = 0; ni < 4; ni++)
#pragma unroll
            for (int e = 0; e < 4; e++) acc[mi][ni][e] = 0.f;

    load_tiles(0, 0); CP_COMMIT();

#pragma unroll 1
    for (int kt = 0; kt < 8; kt++) {
        const int st = kt & 1;
        const int k0 = kt * 32;
        CP_WAIT0();
        __syncthreads();

        {
            char* srcb = smem + OFF_B32 + st * B32_ST;
#pragma unroll
            for (int j = 0; j < 4; j++) {
                const int p = j * 256 + tid;
                const int r = p >> 5, c4 = p & 31;
                float4 v4 = *reinterpret_cast<const float4*>(srcb + r * 528 + c4 * 16);
                __half h0 = __float2half_rn(v4.x), h1 = __float2half_rn(v4.y);
                __half h2 = __float2half_rn(v4.z), h3 = __float2half_rn(v4.w);
                union { __half h[4]; uint2 q; } hh, ll;
                hh.h[0] = h0; hh.h[1] = h1; hh.h[2] = h2; hh.h[3] = h3;
                ll.h[0] = __float2half_rn(v4.x - __half2float(h0));
                ll.h[1] = __float2half_rn(v4.y - __half2float(h1));
                ll.h[2] = __float2half_rn(v4.z - __half2float(h2));
                ll.h[3] = __float2half_rn(v4.w - __half2float(h3));
                *reinterpret_cast<uint2*>(smem + OFF_B16 + r * 272 + c4 * 8) = hh.q;
                *reinterpret_cast<uint2*>(smem + OFF_B16 + B16PL + r * 272 + c4 * 8) = ll.q;
                if (mtile == 0)
                    *reinterpret_cast<uint2*>(uhi_out + (size_t)(k0 + r) * HW + c4 * 4) = hh.q;
            }
        }
        __syncthreads();

        if (kt < 7) { load_tiles(kt + 1, st ^ 1); CP_COMMIT(); }

        const uint32_t uAh = uS + st * A_ST, uAl = uAh + APL;
        const uint32_t uBh = uS + OFF_B16,   uBl = uBh + B16PL;
#pragma unroll
        for (int s = 0; s < 2; s++) {
            uint32_t ah[4][4], al[4][4];
            const uint32_t arow = (uint32_t)(wm * 64 + (lane & 15));
            const uint32_t aoff = 2u * (arow * PITCHA + s * 16 + (lane >> 4) * 8);
#pragma unroll
            for (int mi = 0; mi < 4; mi++) {
                const uint32_t o = aoff + 2u * (mi * 16 * PITCHA);
                ldsm_x4(ah[mi], uAh + o);
                ldsm_x4(al[mi], uAl + o);
            }
            const uint32_t bk = (uint32_t)(s * 16 + (lane & 15));
            const uint32_t brow = 2u * (bk * PITCHB);
#pragma unroll
            for (int ni = 0; ni < 4; ni++) {
                const uint32_t o = brow + 2u * (wn * 32 + ni * 8);
                uint32_t bh[2], bl[2];
                ldsm_x2t(bh, uBh + o);
                ldsm_x2t(bl, uBl + o);
#pragma unroll
                for (int mi = 0; mi < 4; mi++) {
                    mma16816(acc[mi][ni], ah[mi], bh);
                    mma16816(acc[mi][ni], ah[mi], bl);
                    mma16816(acc[mi][ni], al[mi], bh);
                }
            }
        }
    }

    const int qr = lane >> 2, qc = (lane & 3) * 2;
#pragma unroll
    for (int mi = 0; mi < 4; mi++) {
        const int c = mtile * 128 + wm * 64 + mi * 16 + qr;
        const float b0f = bias[c], b1f = bias[c + 8];
        __half* oh0 = g_Hmhi + ((size_t)b * 256 + c) * HW + n0;
        __half* ol0 = g_Hmlo + ((size_t)b * 256 + c) * HW + n0;
#pragma unroll
        for (int ni = 0; ni < 4; ni++) {
            const int n = wn * 32 + ni * 8 + qc;
#pragma unroll
            for (int hf = 0; hf < 2; hf++) {
                const float bb = hf ? b1f : b0f;
                float x0 = fmaxf(acc[mi][ni][hf * 2 + 0] + bb, 0.f);
                float x1 = fmaxf(acc[mi][ni][hf * 2 + 1] + bb, 0.f);
                __half h0 = __float2half_rn(x0);
                __half h1 = __float2half_rn(x1);
                union { __half v[2]; uint32_t q; } hh, ll;
                hh.v[0] = h0; hh.v[1] = h1;
                ll.v[0] = __float2half_rn(x0 - __half2float(h0));
                ll.v[1] = __float2half_rn(x1 - __half2float(h1));
                const size_t off = (size_t)(hf * 8) * HW + n;
                *reinterpret_cast<uint32_t*>(oh0 + off) = hh.q;
                *reinterpret_cast<uint32_t*>(ol0 + off) = ll.q;
            }
        }
    }
}

// ---------------------------------------------------------------------------
// gemm_vf: full batch, ONE kernel. mtile 0,1 = value (1-term, fp16 head-major
// out); mtile 2 = flow (3-term, BM=64). grid (3,128,NB) = 1536 CTAs —
// heterogeneous CTAs pack in the same wave set (in-kernel overlap).
// ---------------------------------------------------------------------------
__global__ __launch_bounds__(256, 2) void gemm_vf(const float* __restrict__ biasV,
                                                  const float* __restrict__ biasF)
{
    extern __shared__ __align__(16) char smem[];
    const uint32_t uS = smem_u32(smem);

    const int tid = threadIdx.x, lane = tid & 31, wid = tid >> 5;
    const int wm = wid >> 2, wn = wid & 3;
    const int mtile = blockIdx.x, ntile = blockIdx.y, b = blockIdx.z;
    const int n0 = ntile * 128;
    const int qr = lane >> 2, qc = (lane & 3) * 2;

    if (mtile < 2) {
        // ================= value path =================
        constexpr int APL   = 128 * PITCHA * 2;
        constexpr int BPL   = 32 * PITCHB * 2;
        constexpr int STAGE = APL + BPL;

        const __half* Ag = g_Ahi + (size_t)(mtile * 128) * 256;
        const __half* Bg = g_Uhi + (size_t)b * 256 * HW + n0;

        auto load_tiles = [&](int kt, int st) {
            const int k0 = kt * 32;
#pragma unroll
            for (int q = tid; q < 512; q += 256) {
                const int r = q >> 2, c8 = (q & 3) * 8;
                cpa16(uS + st * STAGE + (uint32_t)(r * PITCHA + c8) * 2,
                      Ag + (size_t)r * 256 + k0 + c8);
            }
#pragma unroll
            for (int q = tid; q < 512; q += 256) {
                const int r = q >> 4, c8 = (q & 15) * 8;
                cpa16(uS + st * STAGE + APL + (uint32_t)(r * PITCHB + c8) * 2,
                      Bg + (size_t)(k0 + r) * HW + c8);
            }
        };

        float acc[4][4][4];
#pragma unroll
        for (int mi = 0; mi < 4; mi++)
#pragma unroll
            for (int ni = 0; ni < 4; ni++)
#pragma unroll
                for (int e = 0; e < 4; e++) acc[mi][ni][e] = 0.f;

        load_tiles(0, 0); CP_COMMIT();
        load_tiles(1, 1); CP_COMMIT();

#pragma unroll 1
        for (int kt = 0; kt < 8; kt++) {
            const int st = kt % 3;
            if (kt < 7) { CP_WAIT1(); } else { CP_WAIT0(); }
            __syncthreads();

            const uint32_t uAh = uS + (uint32_t)st * STAGE;
            const uint32_t uBh = uAh + APL;
#pragma unroll
            for (int s = 0; s < 2; s++) {
                uint32_t ah[4][4];
                const uint32_t arow = (uint32_t)(wm * 64 + (lane & 15));
                const uint32_t aoff = 2u * (arow * PITCHA + s * 16 + (lane >> 4) * 8);
#pragma unroll
                for (int mi = 0; mi < 4; mi++)
                    ldsm_x4(ah[mi], uAh + aoff + 2u * (mi * 16 * PITCHA));
                const uint32_t bk = (uint32_t)(s * 16 + (lane & 15));
                const uint32_t brow = 2u * (bk * PITCHB);
#pragma unroll
                for (int ni = 0; ni < 4; ni++) {
                    uint32_t bh[2];
                    ldsm_x2t(bh, uBh + brow + 2u * (wn * 32 + ni * 8));
#pragma unroll
                    for (int mi = 0; mi < 4; mi++)
                        mma16816(acc[mi][ni], ah[mi], bh);
                }
            }
            if (kt + 2 < 8) { load_tiles(kt + 2, (kt + 2) % 3); CP_COMMIT(); }
        }

        // epilogue: smem reshuffle -> fp16 head-major
        __syncthreads();
        __half* sv = reinterpret_cast<__half*>(smem);
#pragma unroll
        for (int mi = 0; mi < 4; mi++) {
#pragma unroll
            for (int hf = 0; hf < 2; hf++) {
                const int cl = wm * 64 + mi * 16 + qr + hf * 8;
                const float bb = biasV[mtile * 128 + cl];
                const int hd = cl >> 3, ci = cl & 7;
#pragma unroll
                for (int ni = 0; ni < 4; ni++) {
                    const int n = wn * 32 + ni * 8 + qc;
                    sv[(hd * 128 + n)     * 8 + ci] = __float2half_rn(acc[mi][ni][hf * 2 + 0] + bb);
                    sv[(hd * 128 + n + 1) * 8 + ci] = __float2half_rn(acc[mi][ni][hf * 2 + 1] + bb);
                }
            }
        }
        __syncthreads();
#pragma unroll
        for (int q = tid; q < 2048; q += 256) {
            const int hd = q >> 7, p = q & 127;
            uint4 v = *reinterpret_cast<const uint4*>(sv + (hd * 128 + p) * 8);
            *reinterpret_cast<uint4*>(g_valh +
                (((size_t)b * 32 + mtile * 16 + hd) * HW + n0 + p) * 8) = v;
        }
    } else {
        // ================= flow path =================
        constexpr int ROWS = 64, MI = 2;
        constexpr int APLANE = ROWS * PITCHA * 2;
        constexpr int A_BUF  = 2 * APLANE;
        constexpr int BPLANE = 32 * PITCHB * 2;
        constexpr int STAGE  = A_BUF + 2 * BPLANE;
        constexpr int ACH    = ROWS * 4;

        const __half* Ag[2] = { g_W2hi, g_W2lo };
        const __half* Bg[2] = { g_Hmhi + (size_t)b * 256 * HW + n0,
                                g_Hmlo + (size_t)b * 256 * HW + n0 };

        auto load_tiles = [&](int kt, int st) {
            const int k0 = kt * 32;
#pragma unroll
            for (int q = tid; q < 2 * ACH; q += 256) {
                const int pl = q / ACH, qq = q % ACH;
                const int r = qq >> 2, c8 = (qq & 3) * 8;
                cpa16(uS + st * STAGE + pl * APLANE + (uint32_t)(r * PITCHA + c8) * 2,
                      Ag[pl] + (size_t)r * 256 + k0 + c8);
            }
#pragma unroll
            for (int q = tid; q < 1024; q += 256) {
                const int pl = q >> 9, qq = q & 511;
                const int r = qq >> 4, c8 = (qq & 15) * 8;
                cpa16(uS + st * STAGE + A_BUF + pl * BPLANE + (uint32_t)(r * PITCHB + c8) * 2,
                      Bg[pl] + (size_t)(k0 + r) * HW + c8);
            }
        };

        float acc[MI][4][4];
#pragma unroll
        for (int mi = 0; mi < MI; mi++)
#pragma unroll
            for (int ni = 0; ni < 4; ni++)
#pragma unroll
                for (int e = 0; e < 4; e++) acc[mi][ni][e] = 0.f;

        load_tiles(0, 0); CP_COMMIT();
        load_tiles(1, 1); CP_COMMIT();

#pragma unroll 1
        for (int kt = 0; kt < 8; kt++) {
            const int st = kt % 3;
            if (kt < 7) { CP_WAIT1(); } else { CP_WAIT0(); }
            __syncthreads();

            const uint32_t uAh = uS + (uint32_t)st * STAGE, uAl = uAh + APLANE;
            const uint32_t uBh = uAh + A_BUF,               uBl = uBh + BPLANE;
#pragma unroll
            for (int s = 0; s < 2; s++) {
                uint32_t ah[MI][4], al[MI][4];
                const uint32_t arow = (uint32_t)(wm * 32 + (lane & 15));
                const uint32_t aoff = 2u * (arow * PITCHA + s * 16 + (lane >> 4) * 8);
#pragma unroll
                for (int mi = 0; mi < MI; mi++) {
                    const uint32_t o = aoff + 2u * (mi * 16 * PITCHA);
                    ldsm_x4(ah[mi], uAh + o);
                    ldsm_x4(al[mi], uAl + o);
                }
                const uint32_t bk = (uint32_t)(s * 16 + (lane & 15));
                const uint32_t brow = 2u * (bk * PITCHB);
#pragma unroll
                for (int ni = 0; ni < 4; ni++) {
                    const uint32_t o = brow + 2u * (wn * 32 + ni * 8);
                    uint32_t bh[2], bl[2];
                    ldsm_x2t(bh, uBh + o);
                    ldsm_x2t(bl, uBl + o);
#pragma unroll
                    for (int mi = 0; mi < MI; mi++) {
                        mma16816(acc[mi][ni], ah[mi], bh);
                        mma16816(acc[mi][ni], ah[mi], bl);
                        mma16816(acc[mi][ni], al[mi], bh);
                    }
                }
            }
            if (kt + 2 < 8) { load_tiles(kt + 2, (kt + 2) % 3); CP_COMMIT(); }
        }

#pragma unroll
        for (int mi = 0; mi < MI; mi++) {
            const int m0 = wm * 32 + mi * 16 + qr;
            const float b0f = biasF[m0], b1f = biasF[m0 + 8];
            float* o0 = g_flow + ((size_t)b * 64 + m0) * HW + n0;
            float* o1 = o0 + (size_t)8 * HW;
#pragma unroll
            for (int ni = 0; ni < 4; ni++) {
                const int n = wn * 32 + ni * 8 + qc;
                float2 v0 = {acc[mi][ni][0] + b0f, acc[mi][ni][1] + b0f};
                float2 v1 = {acc[mi][ni][2] + b1f, acc[mi][ni][3] + b1f};
                *(float2*)&o0[n] = v0;
                *(float2*)&o1[n] = v1;
            }
        }
    }
}

// ---------------------------------------------------------------------------
__global__ __launch_bounds__(256)
void warp_gather_kernel(float* __restrict__ out)
{
    const int x = threadIdx.x;
    const int y = blockIdx.x * 2 + threadIdx.y;
    const int bh = blockIdx.y;
    const int b = bh >> 5, head = bh & 31;

    const float* fb = g_flow + ((size_t)b * 64 + head * 2) * HW + y * WDIM + x;
    const float fx = fb[0];
    const float fy = fb[HW];

    const float gx = fmaf((float)x, 2.f / 127.f, -1.f) + fx;
    const float gy = fmaf((float)y, 2.f / 127.f, -1.f) + fy;
    const float ix = (gx + 1.f) * 63.5f;
    const float iy = (gy + 1.f) * 63.5f;

    const float x0f = floorf(ix), y0f = floorf(iy);
    const float dx = ix - x0f, dy = iy - y0f;
    const int x0 = (int)x0f, y0 = (int)y0f;
    const int x1 = x0 + 1,   y1 = y0 + 1;

    const bool vx0 = (x0 >= 0) & (x0 < WDIM);
    const bool vx1 = (x1 >= 0) & (x1 < WDIM);
    const bool vy0 = (y0 >= 0) & (y0 < WDIM);
    const bool vy1 = (y1 >= 0) & (y1 < WDIM);

    const int x0c = min(max(x0, 0), WDIM - 1);
    const int x1c = min(max(x1, 0), WDIM - 1);
    const int y0c = min(max(y0, 0), WDIM - 1);
    const int y1c = min(max(y1, 0), WDIM - 1);

    const float w00 = (1.f - dx) * (1.f - dy) * (float)(vx0 & vy0);
    const float w01 = dx * (1.f - dy)         * (float)(vx1 & vy0);
    const float w10 = (1.f - dx) * dy         * (float)(vx0 & vy1);
    const float w11 = dx * dy                 * (float)(vx1 & vy1);

    const __half* vb = g_valh + ((size_t)b * 32 + head) * HW * 8;
    const uint4 q00 = *reinterpret_cast<const uint4*>(vb + (size_t)(y0c * WDIM + x0c) * 8);
    const uint4 q01 = *reinterpret_cast<const uint4*>(vb + (size_t)(y0c * WDIM + x1c) * 8);
    const uint4 q10 = *reinterpret_cast<const uint4*>(vb + (size_t)(y1c * WDIM + x0c) * 8);
    const uint4 q11 = *reinterpret_cast<const uint4*>(vb + (size_t)(y1c * WDIM + x1c) * 8);

    float r[8];
    {
        const __half2* h00 = reinterpret_cast<const __half2*>(&q00);
        const __half2* h01 = reinterpret_cast<const __half2*>(&q01);
        const __half2* h10 = reinterpret_cast<const __half2*>(&q10);
        const __half2* h11 = reinterpret_cast<const __half2*>(&q11);
#pragma unroll
        for (int j = 0; j < 4; j++) {
            float2 a = __half22float2(h00[j]);
            float2 c = __half22float2(h01[j]);
            float2 d = __half22float2(h10[j]);
            float2 e = __half22float2(h11[j]);
            r[j * 2 + 0] = w00 * a.x + w01 * c.x + w10 * d.x + w11 * e.x;
            r[j * 2 + 1] = w00 * a.y + w01 * c.y + w10 * d.y + w11 * e.y;
        }
    }

    float* ob = out + ((size_t)b * 256 + head * 8) * HW + y * WDIM + x;
#pragma unroll
    for (int ci = 0; ci < 8; ci++)
        ob[(size_t)ci * HW] = r[ci];
}

// ---------------------------------------------------------------------------
extern "C" void kernel_launch(void* const* d_in, const int* in_sizes, int n_in,
                              void* d_out, int out_size)
{
    const float* u  = (const float*)d_in[0];
    const float* w1 = (const float*)d_in[1];
    const float* b1 = (const float*)d_in[2];
    const float* w2 = (const float*)d_in[3];
    const float* b2 = (const float*)d_in[4];
    const float* wv = (const float*)d_in[5];
    const float* bv = (const float*)d_in[6];
    float* out = (float*)d_out;

    constexpr int SM_H  = 2 * (2 * 128 * PITCHA * 2) + 2 * (32 * 528) + 2 * (32 * PITCHB * 2); // 92160
    constexpr int SM_VF = 3 * (2 * 2 * 64 * PITCHA + 2 * 2 * 32 * PITCHB);                     // 82944

    static bool init = false;
    if (!init) {
        cudaFuncSetAttribute(gemm_h,  cudaFuncAttributeMaxDynamicSharedMemorySize, SM_H);
        cudaFuncSetAttribute(gemm_vf, cudaFuncAttributeMaxDynamicSharedMemorySize, SM_VF);
        init = true;
    }

    prep_weights<<<640, 256>>>(w1, wv, w2);
    gemm_h<<<dim3(2, 128, NB), 256, SM_H>>>(u, b1);        // h (+exports uhi)
    gemm_vf<<<dim3(3, 128, NB), 256, SM_VF>>>(bv, b2);     // value + flow packed
    warp_gather_kernel<<<dim3(64, 128), dim3(128, 2)>>>(out);
}